// round 9
// baseline (speedup 1.0000x reference)
#include <cuda_runtime.h>

#define WW 4096
#define HH 4096
#define ROWS 32            // output rows per warp
#define OUTW 60            // output columns per strip (warp loads 64 via float2)
#define NSTRIPS 69         // 69*60 = 4140 >= 4096
#define WARPS 4
#define NTHREADS 128
#define GRIDY 32           // HH / (ROWS * WARPS)
#define NBLOCKS (NSTRIPS * GRIDY)

#define PD 8               // cp.async pipeline depth (rows in flight per warp)
#define NSLOT 16           // ring slots per warp (power of 2, > PD)
#define SLOTB 512          // bytes per slot: 64 pred floats + 64 target floats

__device__ double g_sum_d2 = 0.0;
__device__ double g_sum_G  = 0.0;
__device__ double g_cnt    = 0.0;
__device__ unsigned int g_done = 0u;

__device__ __forceinline__ int reflc(int i) {          // reflect-101, width WW
    if (i < 0) i = -i;
    if (i >= WW) i = 2 * WW - 2 - i;
    return i;
}

__device__ __forceinline__ void cp8(unsigned int smem, const float* g) {
    asm volatile("cp.async.ca.shared.global [%0], [%1], 8;" :: "r"(smem), "l"(g));
}
#define CP_COMMIT() asm volatile("cp.async.commit_group;" ::: "memory")
#define CP_WAIT_PD() asm volatile("cp.async.wait_group 8;" ::: "memory")

struct DT { float2 d, t; };

// Horizontal combined taps on 2 columns: A = [1,4,6,4,1], B = [-1,-2,0,2,1]
__device__ __forceinline__ void hpass2(float2 d, float2& A, float2& B) {
    float wm2 = __shfl_up_sync(0xffffffffu,   d.x, 1);
    float wm1 = __shfl_up_sync(0xffffffffu,   d.y, 1);
    float wp2 = __shfl_down_sync(0xffffffffu, d.x, 1);
    float wp3 = __shfl_down_sync(0xffffffffu, d.y, 1);
    float w0 = d.x, w1 = d.y;
    A.x = fmaf(6.f, w0, fmaf(4.f, wm1 + w1, wm2 + wp2));
    B.x = fmaf(2.f, w1 - wm1, wp2 - wm2);
    A.y = fmaf(6.f, w1, fmaf(4.f, w0 + wp2, wm1 + wp3));
    B.y = fmaf(2.f, wp2 - w0, wp3 - wm1);
}

__device__ __forceinline__ void mse2(float2 d, float2 t, float2 mo,
                                     float& accD2, float& accC) {
    float m;
    m = (t.x > 0.f) ? mo.x : 0.f; accD2 = fmaf(m * d.x, d.x, accD2); accC += m;
    m = (t.y > 0.f) ? mo.y : 0.f; accD2 = fmaf(m * d.y, d.y, accD2); accC += m;
}

__device__ __forceinline__ float vcomp(float b0, float b1, float b2, float b3, float b4,
                                       float a0, float a1, float a3, float a4, float mo) {
    float dx = fmaf(6.f, b2, fmaf(4.f, b1 + b3, b0 + b4));
    float dy = fmaf(2.f, a3 - a1, a4 - a0);
    return mo * fmaf(-dy, dy, dx * dx);
}

// ---------- EDGE band (2 of 69 strips): plain scalar loads, reflect columns ----------
__device__ __noinline__ void run_band_edge(
    const float* __restrict__ pred, const float* __restrict__ target,
    int y0, int c0, int c1, float2 mo,
    float& accD2, float& accC, float& accG)
{
    float2 A0, A1, A2, A3, B0, B1, B2, B3;

    auto load = [&](int r) -> DT {
        const float* pp = pred + (size_t)r * WW;
        const float* tp = target + (size_t)r * WW;
        DT q;
        float t0 = __ldg(tp + c0), p0 = __ldg(pp + c0);
        float t1 = __ldg(tp + c1), p1 = __ldg(pp + c1);
        q.t = make_float2(t0, t1);
        q.d = make_float2(p0 - t0, p1 - t1);
        return q;
    };
    auto proc = [&](const DT& q, bool do_mse) {
        if (do_mse) mse2(q.d, q.t, mo, accD2, accC);
        float2 A4, B4; hpass2(q.d, A4, B4);
        accG += vcomp(B0.x, B1.x, B2.x, B3.x, B4.x, A0.x, A1.x, A3.x, A4.x, mo.x);
        accG += vcomp(B0.y, B1.y, B2.y, B3.y, B4.y, A0.y, A1.y, A3.y, A4.y, mo.y);
        A0 = A1; A1 = A2; A2 = A3; A3 = A4;
        B0 = B1; B1 = B2; B2 = B3; B3 = B4;
    };

    { int r = y0 - 2; if (r < 0) r = -r; DT q = load(r); hpass2(q.d, A0, B0); }
    { int r = y0 - 1; if (r < 0) r = -r; DT q = load(r); hpass2(q.d, A1, B1); }
    { DT q = load(y0);     mse2(q.d, q.t, mo, accD2, accC); hpass2(q.d, A2, B2); }
    { DT q = load(y0 + 1); mse2(q.d, q.t, mo, accD2, accC); hpass2(q.d, A3, B3); }
    #pragma unroll 4
    for (int r = y0 + 2; r < y0 + ROWS; r++) { DT q = load(r); proc(q, true); }
    { int r = y0 + ROWS;     if (r >= HH) r = 2 * HH - 2 - r; DT q = load(r); proc(q, false); }
    { int r = y0 + ROWS + 1; if (r >= HH) r = 2 * HH - 2 - r; DT q = load(r); proc(q, false); }
}

__global__ __launch_bounds__(NTHREADS, 6)
void loss_kernel(const float* __restrict__ pred, const float* __restrict__ target,
                 float* __restrict__ out) {
    __shared__ float stage[WARPS * NSLOT * (SLOTB / 4)];   // 32 KB ring
    __shared__ float s_d2[WARPS], s_g[WARPS], s_c[WARPS];
    __shared__ bool  s_last;

    const int lane = threadIdx.x & 31;
    const int wid  = threadIdx.x >> 5;
    const int s    = blockIdx.x;
    const int y0   = (blockIdx.y * WARPS + wid) * ROWS;

    const int xb   = s * OUTW - 2 + lane * 2;        // 8B-aligned when interior
    const bool inx = (xb >= 0) && (xb + 1 < WW);

    const int outlo = s * OUTW;
    const int outhi = s * OUTW + OUTW - 1;
    float2 mo;
    mo.x = (xb     >= outlo && xb     <= outhi && (unsigned)xb       < WW) ? 1.f : 0.f;
    mo.y = (xb + 1 >= outlo && xb + 1 <= outhi && (unsigned)(xb + 1) < WW) ? 1.f : 0.f;

    float accD2 = 0.f, accC = 0.f, accG = 0.f;

    if (__any_sync(0xffffffffu, !inx)) {
        // edge strip (block-uniform): scalar reflected loads
        run_band_edge(pred, target, y0, reflc(xb), reflc(xb + 1), mo, accD2, accC, accG);
    } else {
        // ---- interior strip: cp.async smem ring, PD rows in flight ----
        const float* predx = pred + xb;
        const float* targx = target + xb;
        const float* srd   = stage + wid * NSLOT * (SLOTB / 4);
        unsigned int swarp =
            (unsigned int)__cvta_generic_to_shared(stage) + wid * NSLOT * SLOTB + lane * 8;

        auto issue = [&](int j) {                     // j: 0..35, row y0-2+j
            int r = y0 - 2 + j;
            r = (r < 0) ? -r : r;
            r = (r >= HH) ? (2 * HH - 2 - r) : r;
            unsigned int sl = swarp + (unsigned)((j & (NSLOT - 1)) * SLOTB);
            cp8(sl,       predx + (size_t)r * WW);
            cp8(sl + 256, targx + (size_t)r * WW);
        };
        auto read = [&](int k) -> DT {                // read own lane's 2+2 floats
            const float* base = srd + (k & (NSLOT - 1)) * (SLOTB / 4) + lane * 2;
            float2 p = *(const float2*)base;
            float2 t = *(const float2*)(base + 64);
            DT q; q.t = t; q.d = make_float2(p.x - t.x, p.y - t.y);
            return q;
        };

        float2 A0, A1, A2, A3, B0, B1, B2, B3;

        #pragma unroll
        for (int j = 0; j < PD; j++) { issue(j); CP_COMMIT(); }

        // prologue k = 0..3 (rows y0-2 .. y0+1)
        { issue(PD + 0); CP_COMMIT(); CP_WAIT_PD(); DT q = read(0); hpass2(q.d, A0, B0); }
        { issue(PD + 1); CP_COMMIT(); CP_WAIT_PD(); DT q = read(1); hpass2(q.d, A1, B1); }
        { issue(PD + 2); CP_COMMIT(); CP_WAIT_PD(); DT q = read(2);
          mse2(q.d, q.t, mo, accD2, accC); hpass2(q.d, A2, B2); }
        { issue(PD + 3); CP_COMMIT(); CP_WAIT_PD(); DT q = read(3);
          mse2(q.d, q.t, mo, accD2, accC); hpass2(q.d, A3, B3); }

        // main k = 4..35 (outputs rows y0 .. y0+31)
        #pragma unroll 4
        for (int k = 4; k < ROWS + 4; k++) {
            if (k + PD < ROWS + 4) issue(k + PD);
            CP_COMMIT();
            CP_WAIT_PD();
            DT q = read(k);
            if (k < ROWS + 2) mse2(q.d, q.t, mo, accD2, accC);
            float2 A4, B4; hpass2(q.d, A4, B4);
            accG += vcomp(B0.x, B1.x, B2.x, B3.x, B4.x, A0.x, A1.x, A3.x, A4.x, mo.x);
            accG += vcomp(B0.y, B1.y, B2.y, B3.y, B4.y, A0.y, A1.y, A3.y, A4.y, mo.y);
            A0 = A1; A1 = A2; A2 = A3; A3 = A4;
            B0 = B1; B1 = B2; B2 = B3; B3 = B4;
        }
    }

    // ---- Reduce ----
    #pragma unroll
    for (int off = 16; off > 0; off >>= 1) {
        accD2 += __shfl_down_sync(0xffffffffu, accD2, off);
        accG  += __shfl_down_sync(0xffffffffu, accG,  off);
        accC  += __shfl_down_sync(0xffffffffu, accC,  off);
    }
    if (lane == 0) { s_d2[wid] = accD2; s_g[wid] = accG; s_c[wid] = accC; }
    __syncthreads();
    if (threadIdx.x == 0) {
        float t2 = 0.f, tg = 0.f, tc = 0.f;
        #pragma unroll
        for (int i = 0; i < WARPS; i++) { t2 += s_d2[i]; tg += s_g[i]; tc += s_c[i]; }
        atomicAdd(&g_sum_d2, (double)t2);
        atomicAdd(&g_sum_G,  (double)tg);
        atomicAdd(&g_cnt,    (double)tc);
        __threadfence();
        unsigned int done = atomicAdd(&g_done, 1u);
        s_last = (done == NBLOCKS - 1);
    }
    __syncthreads();

    if (s_last && threadIdx.x == 0) {
        double sd2 = *(volatile double*)&g_sum_d2;
        double sg  = *(volatile double*)&g_sum_G;
        double n   = *(volatile double*)&g_cnt;
        if (n < 1.0) n = 1.0;
        double mae = sd2 / n;
        double G = sg / (256.0 * (double)WW * (double)HH);   // taps were 16x true
        out[0] = (float)(0.2 * G + 0.8 * mae);
        *(volatile double*)&g_sum_d2 = 0.0;
        *(volatile double*)&g_sum_G  = 0.0;
        *(volatile double*)&g_cnt    = 0.0;
        *(volatile unsigned int*)&g_done = 0u;
    }
}

extern "C" void kernel_launch(void* const* d_in, const int* in_sizes, int n_in,
                              void* d_out, int out_size) {
    const float* pred   = (const float*)d_in[0];
    const float* target = (const float*)d_in[1];
    float* out = (float*)d_out;

    dim3 grid(NSTRIPS, GRIDY);
    loss_kernel<<<grid, NTHREADS>>>(pred, target, out);
}

// round 10
// speedup vs baseline: 1.5185x; 1.5185x over previous
#include <cuda_runtime.h>

#define WW 4096
#define HH 4096
#define ROWS 32            // output rows per warp
#define OUTW 60            // output columns per strip (warp loads 64 via float2)
#define NSTRIPS 69         // 69*60 = 4140 >= 4096
#define WARPS 4
#define NTHREADS 128
#define GRIDY 32           // HH / (ROWS * WARPS)
#define NBLOCKS (NSTRIPS * GRIDY)

typedef unsigned long long u64;

__device__ double g_sum_d2 = 0.0;
__device__ double g_sum_G  = 0.0;
__device__ double g_cnt    = 0.0;
__device__ unsigned int g_done = 0u;

__device__ __forceinline__ int reflc(int i) {          // reflect-101, width WW
    if (i < 0) i = -i;
    if (i >= WW) i = 2 * WW - 2 - i;
    return i;
}

// ---- packed f32x2 helpers (Blackwell FFMA2 path; ptxas won't emit from C++) ----
__device__ __forceinline__ u64 pk(float lo, float hi) {
    u64 r; asm("mov.b64 %0, {%1, %2};" : "=l"(r) : "f"(lo), "f"(hi)); return r;
}
__device__ __forceinline__ u64 add2(u64 a, u64 b) {
    u64 r; asm("add.rn.f32x2 %0, %1, %2;" : "=l"(r) : "l"(a), "l"(b)); return r;
}
__device__ __forceinline__ u64 fma2(u64 a, u64 b, u64 c) {
    u64 r; asm("fma.rn.f32x2 %0, %1, %2, %3;" : "=l"(r) : "l"(a), "l"(b), "l"(c)); return r;
}
__device__ __forceinline__ float2 upk(u64 a) {
    float lo, hi; asm("mov.b64 {%0, %1}, %2;" : "=f"(lo), "=f"(hi) : "l"(a));
    return make_float2(lo, hi);
}

struct DT { float2 d, t; };

// Horizontal combined taps, packed. A = [1,4,6,4,1], B = [-1,-2,0,2,1] on d.
// Column pairs per lane; halo via 4 scalar shuffles.
__device__ __forceinline__ void hpassP(float2 d, u64 dp,
                                       u64 C6, u64 C4, u64 C2, u64 CM1,
                                       u64& A, u64& B) {
    float wm2 = __shfl_up_sync(0xffffffffu,   d.x, 1);
    float wm1 = __shfl_up_sync(0xffffffffu,   d.y, 1);
    float wp2 = __shfl_down_sync(0xffffffffu, d.x, 1);
    float wp3 = __shfl_down_sync(0xffffffffu, d.y, 1);
    u64 P1 = pk(wm1, d.x);
    u64 P2 = pk(d.y, wp2);
    u64 P3 = pk(wm2, wm1);
    u64 P4 = pk(wp2, wp3);
    A = fma2(C6, dp, fma2(C4, add2(P1, P2), add2(P3, P4)));
    B = fma2(C2, fma2(P1, CM1, P2), fma2(P3, CM1, P4));
}

// Whole band, specialized on EDGE. Interior warps: branch-free front-batched
// LDG.64 chunks (R6 structure). All math unmasked; halo lanes zeroed at end.
template <bool EDGE>
__device__ __forceinline__ void run_band(
    const float* __restrict__ pred, const float* __restrict__ target,
    int y0, int xb, int c0, int c1,
    float& accD2, float& accC, u64& accGX, u64& accGY)
{
    const u64 C6  = pk(6.f, 6.f);
    const u64 C4  = pk(4.f, 4.f);
    const u64 C2  = pk(2.f, 2.f);
    const u64 CM1 = pk(-1.f, -1.f);

    u64 A0, A1, A2, A3, B0, B1, B2, B3;

    auto load = [&](const float* __restrict__ pp,
                    const float* __restrict__ tp) -> DT {
        DT r;
        if (EDGE) {
            float t0 = __ldg(tp + c0), p0 = __ldg(pp + c0);
            float t1 = __ldg(tp + c1), p1 = __ldg(pp + c1);
            r.t = make_float2(t0, t1);
            r.d = make_float2(p0 - t0, p1 - t1);
        } else {
            float2 p = __ldg((const float2*)(pp + xb));
            float2 t = __ldg((const float2*)(tp + xb));
            r.t = t;
            r.d = make_float2(p.x - t.x, p.y - t.y);
        }
        return r;
    };

    auto proc = [&](const DT& q, bool do_mse) {
        if (do_mse) {
            if (q.t.x > 0.f) { accD2 = fmaf(q.d.x, q.d.x, accD2); accC += 1.f; }
            if (q.t.y > 0.f) { accD2 = fmaf(q.d.y, q.d.y, accD2); accC += 1.f; }
        }
        u64 dp = pk(q.d.x, q.d.y);
        u64 A4, B4; hpassP(q.d, dp, C6, C4, C2, CM1, A4, B4);
        u64 dx = fma2(C6, B2, fma2(C4, add2(B1, B3), add2(B0, B4)));
        u64 dy = fma2(C2, fma2(A1, CM1, A3), fma2(A0, CM1, A4));
        accGX = fma2(dx, dx, accGX);
        accGY = fma2(dy, dy, accGY);
        A0 = A1; A1 = A2; A2 = A3; A3 = A4;
        B0 = B1; B1 = B2; B2 = B3; B3 = B4;
    };

    auto honly = [&](const DT& q, u64& A, u64& B) {
        u64 dp = pk(q.d.x, q.d.y);
        hpassP(q.d, dp, C6, C4, C2, CM1, A, B);
    };

    // ---- Prologue: rows y0-2 .. y0+1 (top reflect; MSE on last two) ----
    {
        int rm2 = y0 - 2; if (rm2 < 0) rm2 = -rm2;
        int rm1 = y0 - 1; if (rm1 < 0) rm1 = -rm1;
        { DT q = load(pred + rm2 * WW, target + rm2 * WW); honly(q, A0, B0); }
        { DT q = load(pred + rm1 * WW, target + rm1 * WW); honly(q, A1, B1); }
        { DT q = load(pred + y0 * WW, target + y0 * WW);
          if (q.t.x > 0.f) { accD2 = fmaf(q.d.x, q.d.x, accD2); accC += 1.f; }
          if (q.t.y > 0.f) { accD2 = fmaf(q.d.y, q.d.y, accD2); accC += 1.f; }
          honly(q, A2, B2); }
        { DT q = load(pred + (y0 + 1) * WW, target + (y0 + 1) * WW);
          if (q.t.x > 0.f) { accD2 = fmaf(q.d.x, q.d.x, accD2); accC += 1.f; }
          if (q.t.y > 0.f) { accD2 = fmaf(q.d.y, q.d.y, accD2); accC += 1.f; }
          honly(q, A3, B3); }
    }

    // ---- Main: rows y0+2 .. y0+29, 7 chunks x 4 rows, loads front-batched ----
    const float* pp = pred   + (y0 + 2) * WW;
    const float* tp = target + (y0 + 2) * WW;
    #pragma unroll 1
    for (int c = 0; c < 7; c++) {
        DT q0 = load(pp,          tp);
        DT q1 = load(pp + WW,     tp + WW);
        DT q2 = load(pp + 2 * WW, tp + 2 * WW);
        DT q3 = load(pp + 3 * WW, tp + 3 * WW);
        pp += 4 * WW; tp += 4 * WW;
        proc(q0, true); proc(q1, true); proc(q2, true); proc(q3, true);
    }

    // ---- Rows y0+30, y0+31 (core, MSE; always interior) ----
    {
        DT q0 = load(pp,      tp);
        DT q1 = load(pp + WW, tp + WW);
        proc(q0, true); proc(q1, true);
    }

    // ---- Rows y0+32, y0+33 (bottom reflect; halo only) ----
    {
        int ra = y0 + ROWS;     if (ra >= HH) ra = 2 * HH - 2 - ra;
        int rb = y0 + ROWS + 1; if (rb >= HH) rb = 2 * HH - 2 - rb;
        DT q0 = load(pred + ra * WW, target + ra * WW);
        DT q1 = load(pred + rb * WW, target + rb * WW);
        proc(q0, false); proc(q1, false);
    }
}

__global__ __launch_bounds__(NTHREADS, 6)
void loss_kernel(const float* __restrict__ pred, const float* __restrict__ target,
                 float* __restrict__ out) {
    __shared__ float s_d2[WARPS], s_g[WARPS], s_c[WARPS];
    __shared__ bool  s_last;

    const int lane = threadIdx.x & 31;
    const int wid  = threadIdx.x >> 5;
    const int s    = blockIdx.x;
    const int y0   = (blockIdx.y * WARPS + wid) * ROWS;

    const int xb   = s * OUTW - 2 + lane * 2;        // 8B-aligned when interior
    const bool inx = (xb >= 0) && (xb + 1 < WW);

    // Per-lane validity (verified mo.x == mo.y for all lanes/strips):
    const int outlo = s * OUTW;
    const int outhi = s * OUTW + OUTW - 1;
    const float actf =
        (xb >= outlo && xb <= outhi && (unsigned)xb < WW) ? 1.f : 0.f;

    float accD2 = 0.f, accC = 0.f;
    u64 accGX = pk(0.f, 0.f), accGY = pk(0.f, 0.f);

    if (__any_sync(0xffffffffu, !inx))
        run_band<true >(pred, target, y0, xb, reflc(xb), reflc(xb + 1),
                        accD2, accC, accGX, accGY);
    else
        run_band<false>(pred, target, y0, xb, 0, 0,
                        accD2, accC, accGX, accGY);

    // ---- Fold packed accumulators, apply lane mask, reduce ----
    float2 gx = upk(accGX), gy = upk(accGY);
    float accG = ((gx.x + gx.y) - (gy.x + gy.y)) * actf;
    accD2 *= actf;
    accC  *= actf;

    #pragma unroll
    for (int off = 16; off > 0; off >>= 1) {
        accD2 += __shfl_down_sync(0xffffffffu, accD2, off);
        accG  += __shfl_down_sync(0xffffffffu, accG,  off);
        accC  += __shfl_down_sync(0xffffffffu, accC,  off);
    }
    if (lane == 0) { s_d2[wid] = accD2; s_g[wid] = accG; s_c[wid] = accC; }
    __syncthreads();
    if (threadIdx.x == 0) {
        float t2 = 0.f, tg = 0.f, tc = 0.f;
        #pragma unroll
        for (int i = 0; i < WARPS; i++) { t2 += s_d2[i]; tg += s_g[i]; tc += s_c[i]; }
        atomicAdd(&g_sum_d2, (double)t2);
        atomicAdd(&g_sum_G,  (double)tg);
        atomicAdd(&g_cnt,    (double)tc);
        __threadfence();
        unsigned int done = atomicAdd(&g_done, 1u);
        s_last = (done == NBLOCKS - 1);
    }
    __syncthreads();

    if (s_last && threadIdx.x == 0) {
        double sd2 = *(volatile double*)&g_sum_d2;
        double sg  = *(volatile double*)&g_sum_G;
        double n   = *(volatile double*)&g_cnt;
        if (n < 1.0) n = 1.0;
        double mae = sd2 / n;
        double G = sg / (256.0 * (double)WW * (double)HH);   // taps were 16x true
        out[0] = (float)(0.2 * G + 0.8 * mae);
        *(volatile double*)&g_sum_d2 = 0.0;
        *(volatile double*)&g_sum_G  = 0.0;
        *(volatile double*)&g_cnt    = 0.0;
        *(volatile unsigned int*)&g_done = 0u;
    }
}

extern "C" void kernel_launch(void* const* d_in, const int* in_sizes, int n_in,
                              void* d_out, int out_size) {
    const float* pred   = (const float*)d_in[0];
    const float* target = (const float*)d_in[1];
    float* out = (float*)d_out;

    dim3 grid(NSTRIPS, GRIDY);
    loss_kernel<<<grid, NTHREADS>>>(pred, target, out);
}